// round 5
// baseline (speedup 1.0000x reference)
#include <cuda_runtime.h>
#include <cstdint>

// Problem constants (fixed shapes)
#define BQ    28800     // B*Q = 32*900
#define CNUM  92
#define TNUM  2048
#define RB    96        // rows per block tile
#define RBLK  (BQ / RB) // 300 row blocks
#define PSTR  100       // padded row-stride (floats) of transposed prob tile

// Scratch (allocation-free rule: __device__ globals)
// Transposed prob: [block][class][row_in_block], (2 - softmax)
__device__ __align__(16) float  g_probT[RBLK * CNUM * RB];
__device__ __align__(16) float4 g_tf[TNUM * 3];   // {cx,cy,w,h},{x0,y0,x1,y1},{area,label_bits,0,0}

// ---------------------------------------------------------------------------
// Packed f32x2 helpers (Blackwell sm_100+). NOTE: no min/max.f32x2 exists.
// ---------------------------------------------------------------------------
union P2 { unsigned long long u; float2 f; };

__device__ __forceinline__ P2 mk2(float x, float y) { P2 r; r.f = make_float2(x, y); return r; }
__device__ __forceinline__ P2 add2(P2 a, P2 b) { P2 r; asm("add.rn.f32x2 %0,%1,%2;" : "=l"(r.u) : "l"(a.u), "l"(b.u)); return r; }
__device__ __forceinline__ P2 sub2(P2 a, P2 b) { P2 r; asm("sub.rn.f32x2 %0,%1,%2;" : "=l"(r.u) : "l"(a.u), "l"(b.u)); return r; }
__device__ __forceinline__ P2 mul2(P2 a, P2 b) { P2 r; asm("mul.rn.f32x2 %0,%1,%2;" : "=l"(r.u) : "l"(a.u), "l"(b.u)); return r; }
__device__ __forceinline__ P2 fma2(P2 a, P2 b, P2 c) { P2 r; asm("fma.rn.f32x2 %0,%1,%2,%3;" : "=l"(r.u) : "l"(a.u), "l"(b.u), "l"(c.u)); return r; }
__device__ __forceinline__ float frcp(float x) { float r; asm("rcp.approx.ftz.f32 %0,%1;" : "=f"(r) : "f"(x)); return r; }

// ---------------------------------------------------------------------------
// Phase 1: softmax (no max-subtract: logits ~N(0,1), exp safe; tol 1e-3).
// Stores (2 - prob) TRANSPOSED per row-block: g_probT[blk][c][i].
// First 8 blocks also precompute per-target features.
// ---------------------------------------------------------------------------
__global__ __launch_bounds__(256) void prep_kernel(const float* __restrict__ logits,
                                                   const float* __restrict__ tgt_boxes,
                                                   const int*   __restrict__ tgt_labels) {
    if (blockIdx.x < TNUM / 256) {
        int t = blockIdx.x * 256 + threadIdx.x;
        float4 b = reinterpret_cast<const float4*>(tgt_boxes)[t];
        float hw = 0.5f * b.z, hh = 0.5f * b.w;
        g_tf[t * 3 + 0] = b;
        g_tf[t * 3 + 1] = make_float4(b.x - hw, b.y - hh, b.x + hw, b.y + hh);
        g_tf[t * 3 + 2] = make_float4(b.z * b.w, __int_as_float(tgt_labels[t]), 0.f, 0.f);
    }

    int row  = blockIdx.x * 8 + (threadIdx.x >> 5);
    int lane = threadIdx.x & 31;
    if (row >= BQ) return;
    const float* in = logits + (size_t)row * CNUM;

    float e0 = __expf(in[lane]);
    float e1 = __expf(in[lane + 32]);
    float e2 = (lane < 28) ? __expf(in[lane + 64]) : 0.f;

    float s = e0 + e1 + e2;
    #pragma unroll
    for (int o = 16; o > 0; o >>= 1) s += __shfl_xor_sync(0xffffffffu, s, o);

    float inv = __fdividef(1.f, s);

    int blk = row / RB, i = row % RB;
    float* op = g_probT + (size_t)blk * (CNUM * RB) + i;   // + c*RB per class
    op[(size_t)lane * RB]        = 2.f - e0 * inv;
    op[(size_t)(lane + 32) * RB] = 2.f - e1 * inv;
    if (lane < 28) op[(size_t)(lane + 64) * RB] = 2.f - e2 * inv;
}

// ---------------------------------------------------------------------------
// Loop-invariant per-thread state: pack of 2 targets.
// ---------------------------------------------------------------------------
struct TPack {
    P2 cx, cy, w, h, area;          // packed {A,B}
    float ax0, ay0, ax1, ay1;       // target A xyxy (scalar, FMNMX path)
    float bx0, by0, bx1, by1;       // target B xyxy
};

// cost for 2 (row,target) pairs; ga/gb = pre-gathered (2 - prob[row][label]).
__device__ __forceinline__ float2 pack_cost(
    P2 rcx, P2 rcy, P2 rw, P2 rh, P2 rA, float4 rx,
    const TPack& T, float ga, float gb)
{
    // L1: packed subs, scalar abs-adds (abs folds into FADD src modifiers)
    P2 d0 = sub2(rcx, T.cx);
    P2 d1 = sub2(rcy, T.cy);
    P2 d2 = sub2(rw,  T.w);
    P2 d3 = sub2(rh,  T.h);
    float l1a = (fabsf(d0.f.x) + fabsf(d1.f.x)) + (fabsf(d2.f.x) + fabsf(d3.f.x));
    float l1b = (fabsf(d0.f.y) + fabsf(d1.f.y)) + (fabsf(d2.f.y) + fabsf(d3.f.y));

    // Intersection widths (scalar FMNMX), enclosing via eW = (rw+tw) - wiu
    float wiua = fminf(rx.z, T.ax1) - fmaxf(rx.x, T.ax0);
    float wiub = fminf(rx.z, T.bx1) - fmaxf(rx.x, T.bx0);
    float wa = fmaxf(wiua, 0.f), wb = fmaxf(wiub, 0.f);
    P2 eW = sub2(add2(rw, T.w), mk2(wiua, wiub));

    float hiua = fminf(rx.w, T.ay1) - fmaxf(rx.y, T.ay0);
    float hiub = fminf(rx.w, T.by1) - fmaxf(rx.y, T.by0);
    float ha = fmaxf(hiua, 0.f), hb = fmaxf(hiub, 0.f);
    P2 eH = sub2(add2(rh, T.h), mk2(hiua, hiub));

    P2 inter = mul2(mk2(wa, wb), mk2(ha, hb));
    P2 E     = mul2(eW, eH);
    P2 uni   = sub2(add2(rA, T.area), inter);

    // inter/uni + uni/E == (inter*E + uni^2) / (uni*E)  -> one rcp per pair
    P2 num = fma2(inter, E, mul2(uni, uni));
    P2 den = mul2(uni, E);

    float ra = frcp(den.f.x);
    float rb = frcp(den.f.y);
    float resa = fmaf(-2.f, num.f.x * ra, fmaf(5.f, l1a, ga));
    float resb = fmaf(-2.f, num.f.y * rb, fmaf(5.f, l1b, gb));
    return make_float2(resa, resb);
}

// ---------------------------------------------------------------------------
// Phase 2: main cost kernel. 256 threads, 4 targets/thread (2 packs).
// Prob tile staged TRANSPOSED (padded stride) so each thread's class column
// is fetched 4 rows at a time with one LDS.128.
// ---------------------------------------------------------------------------
__global__ __launch_bounds__(256, 2) void cost_kernel(const float* __restrict__ pred_boxes,
                                                      float* __restrict__ out) {
    __shared__ float  sProbT[CNUM * PSTR];  // 92*100*4 = 36800 B  [c*PSTR + i]
    __shared__ float  sDup[RB * 10];        // {cx,cx,cy,cy,w,w,h,h,A,A}
    __shared__ float4 sXY[RB];              // row xyxy

    const int tid = threadIdx.x;
    const int r0  = blockIdx.x * RB;
    const int t0  = blockIdx.y * 1024 + tid * 4;

    // Stage transposed prob tile: contiguous float4 read, near-conflict-free STS
    {
        const float4* gp = reinterpret_cast<const float4*>(
            g_probT + (size_t)blockIdx.x * (CNUM * RB));
        float4* sp = reinterpret_cast<float4*>(sProbT);
        #pragma unroll 1
        for (int j = tid; j < CNUM * (RB / 4); j += 256) {
            int c = j / (RB / 4), i4 = j % (RB / 4);
            sp[c * (PSTR / 4) + i4] = gp[j];
        }
    }
    // Row features
    if (tid < RB) {
        float4 b = reinterpret_cast<const float4*>(pred_boxes)[r0 + tid];
        float* d = sDup + tid * 10;
        d[0] = d[1] = b.x;  d[2] = d[3] = b.y;
        d[4] = d[5] = b.z;  d[6] = d[7] = b.w;
        float a = b.z * b.w; d[8] = d[9] = a;
        float hw = 0.5f * b.z, hh = 0.5f * b.w;
        sXY[tid] = make_float4(b.x - hw, b.y - hh, b.x + hw, b.y + hh);
    }
    __syncthreads();

    // Loop-invariant target packs + labels
    TPack T0, T1;
    int lab[4];
    #pragma unroll
    for (int p = 0; p < 2; p++) {
        TPack& T = p ? T1 : T0;
        int ta = t0 + p * 2, tb = ta + 1;
        float4 A0 = g_tf[ta * 3 + 0], A1 = g_tf[ta * 3 + 1], A2 = g_tf[ta * 3 + 2];
        float4 B0 = g_tf[tb * 3 + 0], B1 = g_tf[tb * 3 + 1], B2 = g_tf[tb * 3 + 2];
        T.cx = mk2(A0.x, B0.x); T.cy = mk2(A0.y, B0.y);
        T.w  = mk2(A0.z, B0.z); T.h  = mk2(A0.w, B0.w);
        T.area = mk2(A2.x, B2.x);
        T.ax0 = A1.x; T.ay0 = A1.y; T.ax1 = A1.z; T.ay1 = A1.w;
        T.bx0 = B1.x; T.by0 = B1.y; T.bx1 = B1.z; T.by1 = B1.w;
        lab[p * 2 + 0] = __float_as_int(A2.y);
        lab[p * 2 + 1] = __float_as_int(B2.y);
    }

    const float4* probT4 = reinterpret_cast<const float4*>(sProbT);
    const int gidx0 = lab[0] * (PSTR / 4);
    const int gidx1 = lab[1] * (PSTR / 4);
    const int gidx2 = lab[2] * (PSTR / 4);
    const int gidx3 = lab[3] * (PSTR / 4);

    float4* op = reinterpret_cast<float4*>(out + (size_t)r0 * TNUM + t0);
    const int strideF4 = TNUM / 4;

    #pragma unroll 1
    for (int w = 0; w < RB / 4; w++) {
        // 4 rows' worth of gathered class costs, one LDS.128 per target
        float4 gA = probT4[gidx0 + w];
        float4 gB = probT4[gidx1 + w];
        float4 gC = probT4[gidx2 + w];
        float4 gD = probT4[gidx3 + w];
        float gAa[4] = {gA.x, gA.y, gA.z, gA.w};
        float gBa[4] = {gB.x, gB.y, gB.z, gB.w};
        float gCa[4] = {gC.x, gC.y, gC.z, gC.w};
        float gDa[4] = {gD.x, gD.y, gD.z, gD.w};

        #pragma unroll
        for (int k = 0; k < 4; k++) {
            const int i = w * 4 + k;
            const P2* rp = reinterpret_cast<const P2*>(sDup + i * 10);
            P2 rcx = rp[0], rcy = rp[1], rw = rp[2], rh = rp[3], rA = rp[4];
            float4 rx = sXY[i];

            float2 resA = pack_cost(rcx, rcy, rw, rh, rA, rx, T0, gAa[k], gBa[k]);
            float2 resB = pack_cost(rcx, rcy, rw, rh, rA, rx, T1, gCa[k], gDa[k]);

            op[(size_t)i * strideF4] = make_float4(resA.x, resA.y, resB.x, resB.y);
        }
    }
}

// ---------------------------------------------------------------------------
extern "C" void kernel_launch(void* const* d_in, const int* in_sizes, int n_in,
                              void* d_out, int out_size) {
    const float* logits  = (const float*)d_in[0];   // [32,900,92] f32
    const float* pboxes  = (const float*)d_in[1];   // [32,900,4]  f32
    const int*   tlabels = (const int*)  d_in[2];   // [2048] i32
    const float* tboxes  = (const float*)d_in[3];   // [2048,4] f32
    float* out = (float*)d_out;                      // [32,900,2048] f32

    prep_kernel<<<BQ / 8, 256>>>(logits, tboxes, tlabels);

    dim3 grid(RBLK, TNUM / 1024);  // (300, 2)
    cost_kernel<<<grid, 256>>>(pboxes, out);
}

// round 6
// speedup vs baseline: 1.0327x; 1.0327x over previous
#include <cuda_runtime.h>
#include <cstdint>

// Problem constants (fixed shapes)
#define BQ    28800     // B*Q = 32*900
#define CNUM  92
#define TNUM  2048
#define RB    96        // rows per block tile
#define RBLK  (BQ / RB) // 300 row blocks
#define PSTR  100       // padded row-stride (floats) of transposed prob tile in cost kernel
#define TSTR  97        // padded stride in prep transpose tile (conflict-free scatter)

// Scratch (allocation-free rule: __device__ globals)
// Transposed prob: [block][class][row_in_block] holding (2 - softmax)
__device__ __align__(16) float  g_probT[RBLK * CNUM * RB];
__device__ __align__(16) float4 g_tf[TNUM * 3];   // {cx,cy,w,h},{x0,y0,x1,y1},{area,label_bits,0,0}

// ---------------------------------------------------------------------------
// Packed f32x2 helpers (Blackwell sm_100+). NOTE: min/max.f32x2 do NOT exist.
// ---------------------------------------------------------------------------
union P2 { unsigned long long u; float2 f; };

__device__ __forceinline__ P2 mk2(float x, float y) { P2 r; r.f = make_float2(x, y); return r; }
__device__ __forceinline__ P2 add2(P2 a, P2 b) { P2 r; asm("add.rn.f32x2 %0,%1,%2;" : "=l"(r.u) : "l"(a.u), "l"(b.u)); return r; }
__device__ __forceinline__ P2 sub2(P2 a, P2 b) { P2 r; asm("sub.rn.f32x2 %0,%1,%2;" : "=l"(r.u) : "l"(a.u), "l"(b.u)); return r; }
__device__ __forceinline__ P2 mul2(P2 a, P2 b) { P2 r; asm("mul.rn.f32x2 %0,%1,%2;" : "=l"(r.u) : "l"(a.u), "l"(b.u)); return r; }
__device__ __forceinline__ P2 fma2(P2 a, P2 b, P2 c) { P2 r; asm("fma.rn.f32x2 %0,%1,%2,%3;" : "=l"(r.u) : "l"(a.u), "l"(b.u), "l"(c.u)); return r; }
__device__ __forceinline__ float frcp(float x) { float r; asm("rcp.approx.ftz.f32 %0,%1;" : "=f"(r) : "f"(x)); return r; }

// ---------------------------------------------------------------------------
// Phase 1: one block per 96-row tile. Warp-per-row softmax (no max-subtract:
// logits ~N(0,1); tol 1e-3), scatter (2-prob) into padded smem tile, then
// write g_probT[blk] with fully coalesced float4 stores.
// First 8 blocks also precompute per-target features.
// ---------------------------------------------------------------------------
__global__ __launch_bounds__(256) void prep_kernel(const float* __restrict__ logits,
                                                   const float* __restrict__ tgt_boxes,
                                                   const int*   __restrict__ tgt_labels) {
    __shared__ float sT[CNUM * TSTR];   // [c*97 + i], ~35.7 KB

    if (blockIdx.x < TNUM / 256) {
        int t = blockIdx.x * 256 + threadIdx.x;
        float4 b = reinterpret_cast<const float4*>(tgt_boxes)[t];
        float hw = 0.5f * b.z, hh = 0.5f * b.w;
        g_tf[t * 3 + 0] = b;
        g_tf[t * 3 + 1] = make_float4(b.x - hw, b.y - hh, b.x + hw, b.y + hh);
        g_tf[t * 3 + 2] = make_float4(b.z * b.w, __int_as_float(tgt_labels[t]), 0.f, 0.f);
    }

    const int warp = threadIdx.x >> 5;
    const int lane = threadIdx.x & 31;
    const int r0   = blockIdx.x * RB;

    // 8 warps x 12 rows = 96 rows
    #pragma unroll 1
    for (int k = 0; k < RB / 8; k++) {
        int i = warp + k * 8;                       // row in tile
        const float* in = logits + (size_t)(r0 + i) * CNUM;

        float e0 = __expf(in[lane]);
        float e1 = __expf(in[lane + 32]);
        float e2 = (lane < 28) ? __expf(in[lane + 64]) : 0.f;

        float s = e0 + e1 + e2;
        #pragma unroll
        for (int o = 16; o > 0; o >>= 1) s += __shfl_xor_sync(0xffffffffu, s, o);
        float inv = __fdividef(1.f, s);

        // scatter: bank = (lane + i) mod 32 -> conflict-free
        sT[lane * TSTR + i]        = 2.f - e0 * inv;
        sT[(lane + 32) * TSTR + i] = 2.f - e1 * inv;
        if (lane < 28) sT[(lane + 64) * TSTR + i] = 2.f - e2 * inv;
    }
    __syncthreads();

    // Coalesced write-out: [c][i] contiguous in i
    float4* gp = reinterpret_cast<float4*>(g_probT + (size_t)blockIdx.x * (CNUM * RB));
    #pragma unroll 1
    for (int j = threadIdx.x; j < CNUM * (RB / 4); j += 256) {
        int c = j / (RB / 4), q = j % (RB / 4);
        const float* s = sT + c * TSTR + q * 4;
        gp[j] = make_float4(s[0], s[1], s[2], s[3]);
    }
}

// ---------------------------------------------------------------------------
// Loop-invariant per-thread state: pack of 2 targets.
// ---------------------------------------------------------------------------
struct TPack {
    P2 cx, cy, w, h, area;          // packed {A,B}
    float ax0, ay0, ax1, ay1;       // target A xyxy (scalar FMNMX path)
    float bx0, by0, bx1, by1;       // target B xyxy
};

// cost for 2 (row,target) pairs; ga/gb = pre-gathered (2 - prob[row][label]).
__device__ __forceinline__ float2 pack_cost(
    P2 rcx, P2 rcy, P2 rw, P2 rh, P2 rA,
    float x0, float y0, float x1, float y1,
    const TPack& T, float ga, float gb)
{
    // L1: packed subs, scalar abs-adds (abs folds into FADD src modifiers)
    P2 d0 = sub2(rcx, T.cx);
    P2 d1 = sub2(rcy, T.cy);
    P2 d2 = sub2(rw,  T.w);
    P2 d3 = sub2(rh,  T.h);
    float l1a = (fabsf(d0.f.x) + fabsf(d1.f.x)) + (fabsf(d2.f.x) + fabsf(d3.f.x));
    float l1b = (fabsf(d0.f.y) + fabsf(d1.f.y)) + (fabsf(d2.f.y) + fabsf(d3.f.y));

    // Intersection widths (scalar FMNMX), enclosing via eW = (rw+tw) - wiu
    float wiua = fminf(x1, T.ax1) - fmaxf(x0, T.ax0);
    float wiub = fminf(x1, T.bx1) - fmaxf(x0, T.bx0);
    float wa = fmaxf(wiua, 0.f), wb = fmaxf(wiub, 0.f);
    P2 eW = sub2(add2(rw, T.w), mk2(wiua, wiub));

    float hiua = fminf(y1, T.ay1) - fmaxf(y0, T.ay0);
    float hiub = fminf(y1, T.by1) - fmaxf(y0, T.by0);
    float ha = fmaxf(hiua, 0.f), hb = fmaxf(hiub, 0.f);
    P2 eH = sub2(add2(rh, T.h), mk2(hiua, hiub));

    P2 inter = mul2(mk2(wa, wb), mk2(ha, hb));
    P2 E     = mul2(eW, eH);
    P2 uni   = sub2(add2(rA, T.area), inter);

    // inter/uni + uni/E == (inter*E + uni^2) / (uni*E)  -> one rcp per pair
    P2 num = fma2(inter, E, mul2(uni, uni));
    P2 den = mul2(uni, E);

    float ra = frcp(den.f.x);
    float rb = frcp(den.f.y);
    float resa = fmaf(-2.f, num.f.x * ra, fmaf(5.f, l1a, ga));
    float resb = fmaf(-2.f, num.f.y * rb, fmaf(5.f, l1b, gb));
    return make_float2(resa, resb);
}

// ---------------------------------------------------------------------------
// Phase 2: main cost kernel. 256 threads, 4 targets/thread (2 packs).
// Row features: 4 broadcast LDS.128 per row. Prob gathers: one LDS.128
// fetches a thread's class value for 4 consecutive rows.
// ---------------------------------------------------------------------------
__global__ __launch_bounds__(256, 2) void cost_kernel(const float* __restrict__ pred_boxes,
                                                      float* __restrict__ out) {
    __shared__ float sProbT[CNUM * PSTR];   // 36800 B  [c*PSTR + i]
    __shared__ float sRow[RB * 16];         // 6144 B: 4 float4 per row

    const int tid = threadIdx.x;
    const int r0  = blockIdx.x * RB;
    const int t0  = blockIdx.y * 1024 + tid * 4;

    // Stage transposed prob tile (contiguous float4 reads, padded STS)
    {
        const float4* gp = reinterpret_cast<const float4*>(
            g_probT + (size_t)blockIdx.x * (CNUM * RB));
        float4* sp = reinterpret_cast<float4*>(sProbT);
        #pragma unroll 1
        for (int j = tid; j < CNUM * (RB / 4); j += 256) {
            int c = j / (RB / 4), i4 = j % (RB / 4);
            sp[c * (PSTR / 4) + i4] = gp[j];
        }
    }
    // Row features: {cx,cx,cy,cy} {w,w,h,h} {A,A,x0,y0} {x1,y1,-,-}
    if (tid < RB) {
        float4 b = reinterpret_cast<const float4*>(pred_boxes)[r0 + tid];
        float4* d = reinterpret_cast<float4*>(sRow + tid * 16);
        float a = b.z * b.w;
        float hw = 0.5f * b.z, hh = 0.5f * b.w;
        d[0] = make_float4(b.x, b.x, b.y, b.y);
        d[1] = make_float4(b.z, b.z, b.w, b.w);
        d[2] = make_float4(a, a, b.x - hw, b.y - hh);
        d[3] = make_float4(b.x + hw, b.y + hh, 0.f, 0.f);
    }
    __syncthreads();

    // Loop-invariant target packs + labels
    TPack T0, T1;
    int lab[4];
    #pragma unroll
    for (int p = 0; p < 2; p++) {
        TPack& T = p ? T1 : T0;
        int ta = t0 + p * 2, tb = ta + 1;
        float4 A0 = g_tf[ta * 3 + 0], A1 = g_tf[ta * 3 + 1], A2 = g_tf[ta * 3 + 2];
        float4 B0 = g_tf[tb * 3 + 0], B1 = g_tf[tb * 3 + 1], B2 = g_tf[tb * 3 + 2];
        T.cx = mk2(A0.x, B0.x); T.cy = mk2(A0.y, B0.y);
        T.w  = mk2(A0.z, B0.z); T.h  = mk2(A0.w, B0.w);
        T.area = mk2(A2.x, B2.x);
        T.ax0 = A1.x; T.ay0 = A1.y; T.ax1 = A1.z; T.ay1 = A1.w;
        T.bx0 = B1.x; T.by0 = B1.y; T.bx1 = B1.z; T.by1 = B1.w;
        lab[p * 2 + 0] = __float_as_int(A2.y);
        lab[p * 2 + 1] = __float_as_int(B2.y);
    }

    const float4* probT4 = reinterpret_cast<const float4*>(sProbT);
    const float4* row4   = reinterpret_cast<const float4*>(sRow);
    const int gidx0 = lab[0] * (PSTR / 4);
    const int gidx1 = lab[1] * (PSTR / 4);
    const int gidx2 = lab[2] * (PSTR / 4);
    const int gidx3 = lab[3] * (PSTR / 4);

    float4* op = reinterpret_cast<float4*>(out + (size_t)r0 * TNUM + t0);
    const int strideF4 = TNUM / 4;

    #pragma unroll 1
    for (int w = 0; w < RB / 4; w++) {
        // 4 rows of gathered class costs, one LDS.128 per target
        float4 gA = probT4[gidx0 + w];
        float4 gB = probT4[gidx1 + w];
        float4 gC = probT4[gidx2 + w];
        float4 gD = probT4[gidx3 + w];
        float gAa[4] = {gA.x, gA.y, gA.z, gA.w};
        float gBa[4] = {gB.x, gB.y, gB.z, gB.w};
        float gCa[4] = {gC.x, gC.y, gC.z, gC.w};
        float gDa[4] = {gD.x, gD.y, gD.z, gD.w};

        #pragma unroll
        for (int k = 0; k < 4; k++) {
            const int i = w * 4 + k;
            float4 f0 = row4[i * 4 + 0];
            float4 f1 = row4[i * 4 + 1];
            float4 f2 = row4[i * 4 + 2];
            float4 f3 = row4[i * 4 + 3];
            P2 rcx = mk2(f0.x, f0.y), rcy = mk2(f0.z, f0.w);
            P2 rw  = mk2(f1.x, f1.y), rh  = mk2(f1.z, f1.w);
            P2 rA  = mk2(f2.x, f2.y);

            float2 resA = pack_cost(rcx, rcy, rw, rh, rA,
                                    f2.z, f2.w, f3.x, f3.y, T0, gAa[k], gBa[k]);
            float2 resB = pack_cost(rcx, rcy, rw, rh, rA,
                                    f2.z, f2.w, f3.x, f3.y, T1, gCa[k], gDa[k]);

            op[(size_t)i * strideF4] = make_float4(resA.x, resA.y, resB.x, resB.y);
        }
    }
}

// ---------------------------------------------------------------------------
extern "C" void kernel_launch(void* const* d_in, const int* in_sizes, int n_in,
                              void* d_out, int out_size) {
    const float* logits  = (const float*)d_in[0];   // [32,900,92] f32
    const float* pboxes  = (const float*)d_in[1];   // [32,900,4]  f32
    const int*   tlabels = (const int*)  d_in[2];   // [2048] i32
    const float* tboxes  = (const float*)d_in[3];   // [2048,4] f32
    float* out = (float*)d_out;                      // [32,900,2048] f32

    prep_kernel<<<RBLK, 256>>>(logits, tboxes, tlabels);

    dim3 grid(RBLK, TNUM / 1024);  // (300, 2)
    cost_kernel<<<grid, 256>>>(pboxes, out);
}

// round 7
// speedup vs baseline: 1.0879x; 1.0534x over previous
#include <cuda_runtime.h>
#include <cstdint>

// Problem constants (fixed shapes)
#define BQ    28800     // B*Q = 32*900
#define CNUM  92
#define TNUM  2048
#define RB    64        // rows per block tile
#define RBLK  (BQ / RB) // 450 row blocks
#define PSTR  68        // padded row-stride (floats) of transposed prob tile in cost kernel
#define TSTR  65        // padded stride in prep transpose tile (conflict-free scatter)

// Scratch (allocation-free rule: __device__ globals)
// Transposed prob: [block][class][row_in_block] holding (2 - softmax)
__device__ __align__(16) float  g_probT[RBLK * CNUM * RB];
__device__ __align__(16) float4 g_tf[TNUM * 3];   // {cx,cy,w,h},{x0,y0,x1,y1},{area,label_bits,0,0}

// ---------------------------------------------------------------------------
// Packed f32x2 helpers (Blackwell sm_100+). NOTE: min/max.f32x2 do NOT exist.
// ---------------------------------------------------------------------------
union P2 { unsigned long long u; float2 f; };

__device__ __forceinline__ P2 mk2(float x, float y) { P2 r; r.f = make_float2(x, y); return r; }
__device__ __forceinline__ P2 add2(P2 a, P2 b) { P2 r; asm("add.rn.f32x2 %0,%1,%2;" : "=l"(r.u) : "l"(a.u), "l"(b.u)); return r; }
__device__ __forceinline__ P2 sub2(P2 a, P2 b) { P2 r; asm("sub.rn.f32x2 %0,%1,%2;" : "=l"(r.u) : "l"(a.u), "l"(b.u)); return r; }
__device__ __forceinline__ P2 mul2(P2 a, P2 b) { P2 r; asm("mul.rn.f32x2 %0,%1,%2;" : "=l"(r.u) : "l"(a.u), "l"(b.u)); return r; }
__device__ __forceinline__ P2 fma2(P2 a, P2 b, P2 c) { P2 r; asm("fma.rn.f32x2 %0,%1,%2,%3;" : "=l"(r.u) : "l"(a.u), "l"(b.u), "l"(c.u)); return r; }
__device__ __forceinline__ float frcp(float x) { float r; asm("rcp.approx.ftz.f32 %0,%1;" : "=f"(r) : "f"(x)); return r; }

// ---------------------------------------------------------------------------
// Phase 1: one block per 64-row tile. Warp-per-row softmax (no max-subtract:
// logits ~N(0,1); tol 1e-3), scatter (2-prob) into padded smem tile, then
// write g_probT[blk] with fully coalesced float4 stores.
// First 8 blocks also precompute per-target features.
// ---------------------------------------------------------------------------
__global__ __launch_bounds__(256) void prep_kernel(const float* __restrict__ logits,
                                                   const float* __restrict__ tgt_boxes,
                                                   const int*   __restrict__ tgt_labels) {
    __shared__ float sT[CNUM * TSTR];   // [c*65 + i], ~23.9 KB

    if (blockIdx.x < TNUM / 256) {
        int t = blockIdx.x * 256 + threadIdx.x;
        float4 b = reinterpret_cast<const float4*>(tgt_boxes)[t];
        float hw = 0.5f * b.z, hh = 0.5f * b.w;
        g_tf[t * 3 + 0] = b;
        g_tf[t * 3 + 1] = make_float4(b.x - hw, b.y - hh, b.x + hw, b.y + hh);
        g_tf[t * 3 + 2] = make_float4(b.z * b.w, __int_as_float(tgt_labels[t]), 0.f, 0.f);
    }

    const int warp = threadIdx.x >> 5;
    const int lane = threadIdx.x & 31;
    const int r0   = blockIdx.x * RB;

    // 8 warps x 8 rows = 64 rows
    #pragma unroll 1
    for (int k = 0; k < RB / 8; k++) {
        int i = warp + k * 8;                       // row in tile
        const float* in = logits + (size_t)(r0 + i) * CNUM;

        float e0 = __expf(in[lane]);
        float e1 = __expf(in[lane + 32]);
        float e2 = (lane < 28) ? __expf(in[lane + 64]) : 0.f;

        float s = e0 + e1 + e2;
        #pragma unroll
        for (int o = 16; o > 0; o >>= 1) s += __shfl_xor_sync(0xffffffffu, s, o);
        float inv = __fdividef(1.f, s);

        // scatter: bank = (lane + i) mod 32 -> conflict-free (TSTR%32==1)
        sT[lane * TSTR + i]        = 2.f - e0 * inv;
        sT[(lane + 32) * TSTR + i] = 2.f - e1 * inv;
        if (lane < 28) sT[(lane + 64) * TSTR + i] = 2.f - e2 * inv;
    }
    __syncthreads();

    // Coalesced write-out: [c][i] contiguous in i
    float4* gp = reinterpret_cast<float4*>(g_probT + (size_t)blockIdx.x * (CNUM * RB));
    #pragma unroll 1
    for (int j = threadIdx.x; j < CNUM * (RB / 4); j += 256) {
        int c = j / (RB / 4), q = j % (RB / 4);
        const float* s = sT + c * TSTR + q * 4;
        gp[j] = make_float4(s[0], s[1], s[2], s[3]);
    }
}

// ---------------------------------------------------------------------------
// Loop-invariant per-thread state: pack of 2 targets.
// ---------------------------------------------------------------------------
struct TPack {
    P2 cx, cy, w, h, area;          // packed {A,B}
    float ax0, ay0, ax1, ay1;       // target A xyxy (scalar FMNMX path)
    float bx0, by0, bx1, by1;       // target B xyxy
};

// cost for 2 (row,target) pairs; ga/gb = pre-gathered (2 - prob[row][label]).
__device__ __forceinline__ float2 pack_cost(
    P2 rcx, P2 rcy, P2 rw, P2 rh, P2 rA, float4 rx,
    const TPack& T, float ga, float gb)
{
    // L1: packed subs, scalar abs-adds (abs folds into FADD src modifiers)
    P2 d0 = sub2(rcx, T.cx);
    P2 d1 = sub2(rcy, T.cy);
    P2 d2 = sub2(rw,  T.w);
    P2 d3 = sub2(rh,  T.h);
    float l1a = (fabsf(d0.f.x) + fabsf(d1.f.x)) + (fabsf(d2.f.x) + fabsf(d3.f.x));
    float l1b = (fabsf(d0.f.y) + fabsf(d1.f.y)) + (fabsf(d2.f.y) + fabsf(d3.f.y));

    // Intersection widths (scalar FMNMX), enclosing via eW = (rw+tw) - wiu
    float wiua = fminf(rx.z, T.ax1) - fmaxf(rx.x, T.ax0);
    float wiub = fminf(rx.z, T.bx1) - fmaxf(rx.x, T.bx0);
    float wa = fmaxf(wiua, 0.f), wb = fmaxf(wiub, 0.f);
    P2 eW = sub2(add2(rw, T.w), mk2(wiua, wiub));

    float hiua = fminf(rx.w, T.ay1) - fmaxf(rx.y, T.ay0);
    float hiub = fminf(rx.w, T.by1) - fmaxf(rx.y, T.by0);
    float ha = fmaxf(hiua, 0.f), hb = fmaxf(hiub, 0.f);
    P2 eH = sub2(add2(rh, T.h), mk2(hiua, hiub));

    P2 inter = mul2(mk2(wa, wb), mk2(ha, hb));
    P2 E     = mul2(eW, eH);
    P2 uni   = sub2(add2(rA, T.area), inter);

    // inter/uni + uni/E == (inter*E + uni^2) / (uni*E)  -> one rcp per pair
    P2 num = fma2(inter, E, mul2(uni, uni));
    P2 den = mul2(uni, E);

    float ra = frcp(den.f.x);
    float rb = frcp(den.f.y);
    float resa = fmaf(-2.f, num.f.x * ra, fmaf(5.f, l1a, ga));
    float resb = fmaf(-2.f, num.f.y * rb, fmaf(5.f, l1b, gb));
    return make_float2(resa, resb);
}

// ---------------------------------------------------------------------------
// Phase 2: main cost kernel. 256 threads, 4 targets/thread (2 packs),
// 64-row tile, 3 CTAs/SM (grid 900 = 2.03 balanced waves at occ 3).
// Row feats via direct LDS.64 -> aligned P2 pairs (no repacking MOVs).
// ---------------------------------------------------------------------------
__global__ __launch_bounds__(256, 3) void cost_kernel(const float* __restrict__ pred_boxes,
                                                      float* __restrict__ out) {
    __shared__ float  sProbT[CNUM * PSTR];  // 92*68*4 = 25024 B  [c*PSTR + i]
    __shared__ float  sDup[RB * 10];        // {cx,cx,cy,cy,w,w,h,h,A,A}  2560 B
    __shared__ float4 sXY[RB];              // row xyxy                  1024 B

    const int tid = threadIdx.x;
    const int r0  = blockIdx.x * RB;
    const int t0  = blockIdx.y * 1024 + tid * 4;

    // Stage transposed prob tile (contiguous float4 reads, padded STS)
    {
        const float4* gp = reinterpret_cast<const float4*>(
            g_probT + (size_t)blockIdx.x * (CNUM * RB));
        float4* sp = reinterpret_cast<float4*>(sProbT);
        #pragma unroll 1
        for (int j = tid; j < CNUM * (RB / 4); j += 256) {
            int c = j / (RB / 4), i4 = j % (RB / 4);
            sp[c * (PSTR / 4) + i4] = gp[j];
        }
    }
    // Row features (duplicated for packed math) + xyxy
    if (tid < RB) {
        float4 b = reinterpret_cast<const float4*>(pred_boxes)[r0 + tid];
        float* d = sDup + tid * 10;
        d[0] = d[1] = b.x;  d[2] = d[3] = b.y;
        d[4] = d[5] = b.z;  d[6] = d[7] = b.w;
        float a = b.z * b.w; d[8] = d[9] = a;
        float hw = 0.5f * b.z, hh = 0.5f * b.w;
        sXY[tid] = make_float4(b.x - hw, b.y - hh, b.x + hw, b.y + hh);
    }
    __syncthreads();

    // Loop-invariant target packs + labels
    TPack T0, T1;
    int lab[4];
    #pragma unroll
    for (int p = 0; p < 2; p++) {
        TPack& T = p ? T1 : T0;
        int ta = t0 + p * 2, tb = ta + 1;
        float4 A0 = g_tf[ta * 3 + 0], A1 = g_tf[ta * 3 + 1], A2 = g_tf[ta * 3 + 2];
        float4 B0 = g_tf[tb * 3 + 0], B1 = g_tf[tb * 3 + 1], B2 = g_tf[tb * 3 + 2];
        T.cx = mk2(A0.x, B0.x); T.cy = mk2(A0.y, B0.y);
        T.w  = mk2(A0.z, B0.z); T.h  = mk2(A0.w, B0.w);
        T.area = mk2(A2.x, B2.x);
        T.ax0 = A1.x; T.ay0 = A1.y; T.ax1 = A1.z; T.ay1 = A1.w;
        T.bx0 = B1.x; T.by0 = B1.y; T.bx1 = B1.z; T.by1 = B1.w;
        lab[p * 2 + 0] = __float_as_int(A2.y);
        lab[p * 2 + 1] = __float_as_int(B2.y);
    }

    const float4* probT4 = reinterpret_cast<const float4*>(sProbT);
    const int gidx0 = lab[0] * (PSTR / 4);
    const int gidx1 = lab[1] * (PSTR / 4);
    const int gidx2 = lab[2] * (PSTR / 4);
    const int gidx3 = lab[3] * (PSTR / 4);

    float4* op = reinterpret_cast<float4*>(out + (size_t)r0 * TNUM + t0);
    const int strideF4 = TNUM / 4;

    #pragma unroll 1
    for (int w = 0; w < RB / 4; w++) {
        // 4 rows of gathered class costs, one LDS.128 per target
        float4 gA = probT4[gidx0 + w];
        float4 gB = probT4[gidx1 + w];
        float4 gC = probT4[gidx2 + w];
        float4 gD = probT4[gidx3 + w];
        float gAa[4] = {gA.x, gA.y, gA.z, gA.w};
        float gBa[4] = {gB.x, gB.y, gB.z, gB.w};
        float gCa[4] = {gC.x, gC.y, gC.z, gC.w};
        float gDa[4] = {gD.x, gD.y, gD.z, gD.w};

        #pragma unroll
        for (int k = 0; k < 4; k++) {
            const int i = w * 4 + k;
            const P2* rp = reinterpret_cast<const P2*>(sDup + i * 10);
            P2 rcx = rp[0], rcy = rp[1], rw = rp[2], rh = rp[3], rA = rp[4];
            float4 rx = sXY[i];

            float2 resA = pack_cost(rcx, rcy, rw, rh, rA, rx, T0, gAa[k], gBa[k]);
            float2 resB = pack_cost(rcx, rcy, rw, rh, rA, rx, T1, gCa[k], gDa[k]);

            op[(size_t)i * strideF4] = make_float4(resA.x, resA.y, resB.x, resB.y);
        }
    }
}

// ---------------------------------------------------------------------------
extern "C" void kernel_launch(void* const* d_in, const int* in_sizes, int n_in,
                              void* d_out, int out_size) {
    const float* logits  = (const float*)d_in[0];   // [32,900,92] f32
    const float* pboxes  = (const float*)d_in[1];   // [32,900,4]  f32
    const int*   tlabels = (const int*)  d_in[2];   // [2048] i32
    const float* tboxes  = (const float*)d_in[3];   // [2048,4] f32
    float* out = (float*)d_out;                      // [32,900,2048] f32

    prep_kernel<<<RBLK, 256>>>(logits, tboxes, tlabels);

    dim3 grid(RBLK, TNUM / 1024);  // (450, 2) = 900 blocks
    cost_kernel<<<grid, 256>>>(pboxes, out);
}